// round 13
// baseline (speedup 1.0000x reference)
#include <cuda_runtime.h>
#include <cuda_bf16.h>
#include <cstdint>
#include <math.h>

// NT-Xent loss, N=4096, D=256, T=0.5. bf16 mma.sync m16n8k16, upper-triangle,
// mbarrier-pipelined persistent kernel (R6 trunk, best known hot loop),
// with the final scalar reduction fused into the sim kernel (last CTA).

#define NROW 8192
#define NHALF 4096
#define DIM 256
#define NTILE 64
#define TOTAL_UT 2080               // 64*65/2
#define C2 2.885390081777927f       // 2 * log2(e)
#define NB 148

// smem: swizzled 512B-row bf16 tiles (64KB each): A + B0 + B1 + mbarriers
#define SM_A 0
#define SM_B0 65536
#define SM_B1 131072
#define SM_BAR 196608
#define SMEM_TOTAL (196608 + 64)

__device__ __nv_bfloat16 g_zh[NROW * DIM];
__device__ float g_denom[NROW];
__device__ float g_pos[NHALF];
__device__ float g_self[NROW];
__device__ unsigned int g_done;

// ---------------------------------------------------------------------------
__device__ __forceinline__ float ex2f(float x) {
    float y; asm("ex2.approx.ftz.f32 %0, %1;" : "=f"(y) : "f"(x)); return y;
}
__device__ __forceinline__ uint32_t smem_u32(const void* p) {
    uint32_t a;
    asm("{ .reg .u64 t; cvta.to.shared.u64 t, %1; cvt.u32.u64 %0, t; }"
        : "=r"(a) : "l"(p));
    return a;
}
__device__ __forceinline__ void cp16(uint32_t s, const void* g) {
    asm volatile("cp.async.cg.shared.global [%0], [%1], 16;" :: "r"(s), "l"(g));
}
#define CP_COMMIT() asm volatile("cp.async.commit_group;" ::: "memory")
#define CP_WAIT0()  asm volatile("cp.async.wait_group 0;" ::: "memory")

#define MBAR_INIT(a, c) \
    asm volatile("mbarrier.init.shared.b64 [%0], %1;" :: "r"(a), "r"(c) : "memory")
#define MBAR_INVAL(a) \
    asm volatile("mbarrier.inval.shared.b64 [%0];" :: "r"(a) : "memory")
#define MBAR_ARRIVE(a) \
    asm volatile("mbarrier.arrive.shared.b64 _, [%0];" :: "r"(a) : "memory")
#define CPA_NOINC(a) \
    asm volatile("cp.async.mbarrier.arrive.noinc.shared.b64 [%0];" :: "r"(a) : "memory")

#define MBAR_WAIT(mbar, ph) do {                                              \
    uint32_t _m = (mbar); uint32_t _p = (uint32_t)(ph); uint32_t _done;       \
    asm volatile("{\n\t.reg .pred p;\n\t"                                     \
        "mbarrier.try_wait.parity.shared.b64 p, [%1], %2;\n\t"                \
        "selp.b32 %0, 1, 0, p;\n\t}"                                          \
        : "=r"(_done) : "r"(_m), "r"(_p) : "memory");                         \
    if (!_done) {                                                             \
        asm volatile("{\n\t.reg .pred P1;\n\t"                                \
            "WL_%=:\n\t"                                                      \
            "mbarrier.try_wait.parity.shared.b64 P1, [%0], %1;\n\t"           \
            "@P1 bra.uni WD_%=;\n\t"                                          \
            "bra.uni WL_%=;\n\t"                                              \
            "WD_%=:\n\t}" :: "r"(_m), "r"(_p) : "memory");                    \
    }                                                                         \
} while (0)

#define LDSM4(r0, r1, r2, r3, a)                                        \
    asm volatile("ldmatrix.sync.aligned.m8n8.x4.shared.b16 "            \
                 "{%0,%1,%2,%3}, [%4];"                                 \
                 : "=r"(r0), "=r"(r1), "=r"(r2), "=r"(r3) : "r"(a))

#define MMA16816(c, a, b0, b1)                                          \
    asm volatile("mma.sync.aligned.m16n8k16.row.col.f32.bf16.bf16.f32 " \
                 "{%0,%1,%2,%3}, {%4,%5,%6,%7}, {%8,%9}, {%0,%1,%2,%3};"\
                 : "+f"((c)[0]), "+f"((c)[1]), "+f"((c)[2]), "+f"((c)[3]) \
                 : "r"((a)[0]), "r"((a)[1]), "r"((a)[2]), "r"((a)[3]),  \
                   "r"(b0), "r"(b1))

// ---------------------------------------------------------------------------
// Kernel 1: normalize (warp per row); bf16 z, self-sim, fp32 positives.
// grid = 1024 x 256.
// ---------------------------------------------------------------------------
__global__ void norm_pos_kernel(const float* __restrict__ ei,
                                const float* __restrict__ ej) {
    const int tid = threadIdx.x, w = tid >> 5, lane = tid & 31;
    const int half = w >> 2;
    const int k = blockIdx.x * 4 + (w & 3);
    const int row = k + half * NHALF;
    const float* src = (half ? ej : ei) + (size_t)k * DIM + lane * 8;

    if (blockIdx.x == 0 && tid == 0) g_done = 0;

    float4 v0 = *reinterpret_cast<const float4*>(src);
    float4 v1 = *reinterpret_cast<const float4*>(src + 4);
    float vf[8] = {v0.x, v0.y, v0.z, v0.w, v1.x, v1.y, v1.z, v1.w};

    float s = 0.f;
    #pragma unroll
    for (int i = 0; i < 8; i++) s += vf[i] * vf[i];
    #pragma unroll
    for (int o = 16; o; o >>= 1) s += __shfl_xor_sync(~0u, s, o);
    const float inv = 1.0f / fmaxf(sqrtf(s), 1e-8f);

    float zf[8];
    __nv_bfloat162 zb[4];
    float ss = 0.f;
    #pragma unroll
    for (int i = 0; i < 8; i++) zf[i] = vf[i] * inv;
    #pragma unroll
    for (int i = 0; i < 4; i++) {
        zb[i] = __floats2bfloat162_rn(zf[2 * i], zf[2 * i + 1]);
        float lo = __bfloat162float(zb[i].x), hi = __bfloat162float(zb[i].y);
        ss += lo * lo + hi * hi;
    }
    *reinterpret_cast<uint4*>(&g_zh[(size_t)row * DIM + lane * 8]) =
        *reinterpret_cast<uint4*>(zb);
    #pragma unroll
    for (int o = 16; o; o >>= 1) ss += __shfl_xor_sync(~0u, ss, o);
    if (lane == 0) { g_self[row] = ss; g_denom[row] = 0.f; }

    __shared__ float zsh[4][DIM];
    if (half == 0) {
        #pragma unroll
        for (int i = 0; i < 8; i++) zsh[w & 3][lane * 8 + i] = zf[i];
    }
    __syncthreads();
    if (half == 1) {
        float p = 0.f;
        #pragma unroll
        for (int i = 0; i < 8; i++) p += zsh[w & 3][lane * 8 + i] * zf[i];
        #pragma unroll
        for (int o = 16; o; o >>= 1) p += __shfl_xor_sync(~0u, p, o);
        if (lane == 0) g_pos[k] = p;
    }
}

// ---------------------------------------------------------------------------
// cp.async of a 128x256 bf16 tile into 512B-row smem, 16B-chunk XOR swizzle
// (chunk c of row r stored at c ^ (r&7)). 256 threads, 16 chunks each.
// ---------------------------------------------------------------------------
__device__ __forceinline__ void fill_tile(uint32_t sdst, int zrow, int tid) {
    const __nv_bfloat16* src = g_zh + ((size_t)zrow << 8);
    #pragma unroll
    for (int i = 0; i < 16; ++i) {
        int q = tid + (i << 8);          // 16B chunk id 0..4095
        int r = q >> 5;                  // row 0..127
        int c = q & 31;
        cp16(sdst + (r << 9) + ((c ^ (r & 7)) << 4), src + ((size_t)q << 3));
    }
}

// ---------------------------------------------------------------------------
// Kernel 2: persistent upper-tri sim-GEMM + exp-sum, mbarrier-pipelined,
// with fused final scalar reduction. 148 CTAs x 256 threads;
// 8 warps = 2(M) x 4(N); warp tile 64x32.
// ---------------------------------------------------------------------------
__global__ __launch_bounds__(256, 1) void sim_kernel(float* __restrict__ out) {
    extern __shared__ char smem[];
    const uint32_t sb = smem_u32(smem);
    const uint32_t FULL[2]  = {sb + SM_BAR,      sb + SM_BAR + 8};
    const uint32_t EMPTY[2] = {sb + SM_BAR + 16, sb + SM_BAR + 24};
    const uint32_t BUF[2]   = {sb + SM_B0, sb + SM_B1};
    const int tid = threadIdx.x, wid = tid >> 5, lane = tid & 31;
    const int wm = wid >> 2, wn = wid & 3;

    const int b = blockIdx.x, nb = gridDim.x;
    const int t0 = (b * TOTAL_UT) / nb;
    const int t1 = ((b + 1) * TOTAL_UT) / nb;
    const int nt = t1 - t0;

    int R = 0, rem = t0;
    while (rem >= NTILE - R) { rem -= NTILE - R; R++; }
    int C = R + rem;

    if (tid == 0) {
        MBAR_INIT(FULL[0], 256); MBAR_INIT(FULL[1], 256);
        MBAR_INIT(EMPTY[0], 256); MBAR_INIT(EMPTY[1], 256);
    }
    __syncthreads();

    // per-lane ldmatrix address precompute (swizzled layout)
    const uint32_t rm  = (uint32_t)(lane & 7) << 4;        // row&7 XOR mask
    const uint32_t hiA = (uint32_t)(lane >> 4) << 4;
    const uint32_t hiB = (uint32_t)((lane >> 3) & 1) << 4;
    uint32_t aRow[4];
    #pragma unroll
    for (int mf = 0; mf < 4; ++mf)
        aRow[mf] = (uint32_t)(wm * 64 + (lane & 15) + mf * 16) << 9;
    const uint32_t rB0 = (uint32_t)(wn * 32 + (lane & 7) + ((lane >> 4) << 3));
    const uint32_t bRow0 = rB0 << 9, bRow1 = (rB0 + 16) << 9;

    float dacc[4][2];
    #pragma unroll
    for (int i = 0; i < 4; i++) { dacc[i][0] = 0.f; dacc[i][1] = 0.f; }

    int loadedR = R;
    fill_tile(sb + SM_A, R << 7, tid);
    fill_tile(BUF[0], C << 7, tid);
    CPA_NOINC(FULL[0]);
    CP_COMMIT(); CP_WAIT0();
    __syncthreads();                     // A (and fill0) visible to all

    for (int i = 0; i < nt; ++i) {
        int Rn = R, Cn = C + 1;
        if (Cn == NTILE) { Rn = R + 1; Cn = Rn; }

        if (R != loadedR) {              // rare: flush + reload A (synced)
            #pragma unroll
            for (int mf = 0; mf < 4; ++mf)
                #pragma unroll
                for (int h = 0; h < 2; ++h) {
                    float v = dacc[mf][h];
                    v += __shfl_xor_sync(~0u, v, 1);
                    v += __shfl_xor_sync(~0u, v, 2);
                    if ((lane & 3) == 0)
                        atomicAdd(&g_denom[(loadedR << 7) + wm * 64 + mf * 16
                                           + (lane >> 2) + h * 8], v);
                    dacc[mf][h] = 0.f;
                }
            __syncthreads();
            fill_tile(sb + SM_A, R << 7, tid);
            CP_COMMIT(); CP_WAIT0();
            __syncthreads();
            loadedR = R;
        }

        // prefetch fill i+1 (buffer free after use i-1's k-loop)
        if (i + 1 < nt) {
            const int nbuf = (i + 1) & 1;
            if (i + 1 >= 2)
                MBAR_WAIT(EMPTY[nbuf], ((((i + 1) >> 1) - 1) & 1));
            fill_tile(BUF[nbuf], Cn << 7, tid);
            CPA_NOINC(FULL[nbuf]);
        }

        // consume tile i
        const int cb = i & 1;
        MBAR_WAIT(FULL[cb], (i >> 1) & 1);
        const uint32_t aBase = sb + SM_A;
        const uint32_t bBase = BUF[cb];

        float acc[4][4][4];
        #pragma unroll
        for (int x = 0; x < 4; x++)
            #pragma unroll
            for (int y = 0; y < 4; y++)
                #pragma unroll
                for (int c = 0; c < 4; c++) acc[x][y][c] = 0.f;

        #pragma unroll
        for (int s = 0; s < 16; ++s) {
            const uint32_t offA = (((uint32_t)s << 5) + hiA) ^ rm;
            const uint32_t offB = (((uint32_t)s << 5) + hiB) ^ rm;
            uint32_t a[4][4];
            #pragma unroll
            for (int mf = 0; mf < 4; ++mf)
                LDSM4(a[mf][0], a[mf][1], a[mf][2], a[mf][3],
                      aBase + aRow[mf] + offA);
            uint32_t bq[2][4];
            LDSM4(bq[0][0], bq[0][1], bq[0][2], bq[0][3], bBase + bRow0 + offB);
            LDSM4(bq[1][0], bq[1][1], bq[1][2], bq[1][3], bBase + bRow1 + offB);
            #pragma unroll
            for (int mf = 0; mf < 4; ++mf)
                #pragma unroll
                for (int nf = 0; nf < 4; ++nf)
                    MMA16816(acc[mf][nf], a[mf],
                             bq[nf >> 1][(nf & 1) * 2],
                             bq[nf >> 1][(nf & 1) * 2 + 1]);
        }
        MBAR_ARRIVE(EMPTY[cb]);          // done reading this B buffer

        // epilogue (overlaps other warps' MMA): rows -> dacc; cols -> colacc
        const bool offDiag = (C != R);
        float colacc[4][2];
        #pragma unroll
        for (int x = 0; x < 4; x++) { colacc[x][0] = 0.f; colacc[x][1] = 0.f; }

        #pragma unroll
        for (int mf = 0; mf < 4; ++mf)
            #pragma unroll
            for (int nf = 0; nf < 4; ++nf)
                #pragma unroll
                for (int c = 0; c < 4; ++c) {
                    float e = ex2f(acc[mf][nf][c] * C2);
                    dacc[mf][c >> 1] += e;
                    colacc[nf][c & 1] += e;
                }

        if (offDiag) {
            #pragma unroll
            for (int nf = 0; nf < 4; ++nf)
                #pragma unroll
                for (int p = 0; p < 2; ++p) {
                    float v = colacc[nf][p];
                    v += __shfl_xor_sync(~0u, v, 4);
                    v += __shfl_xor_sync(~0u, v, 8);
                    v += __shfl_xor_sync(~0u, v, 16);
                    if (lane < 4)
                        atomicAdd(&g_denom[(C << 7) + wn * 32 + nf * 8
                                           + (lane & 3) * 2 + p], v);
                }
        }

        R = Rn; C = Cn;
    }

    // final row flush
    #pragma unroll
    for (int mf = 0; mf < 4; ++mf)
        #pragma unroll
        for (int h = 0; h < 2; ++h) {
            float v = dacc[mf][h];
            v += __shfl_xor_sync(~0u, v, 1);
            v += __shfl_xor_sync(~0u, v, 2);
            if ((lane & 3) == 0)
                atomicAdd(&g_denom[(loadedR << 7) + wm * 64 + mf * 16
                                   + (lane >> 2) + h * 8], v);
        }

    __syncthreads();
    if (tid == 0) {
        MBAR_INVAL(FULL[0]); MBAR_INVAL(FULL[1]);
        MBAR_INVAL(EMPTY[0]); MBAR_INVAL(EMPTY[1]);
    }

    // ---- fused finish: last CTA reduces the scalar ----
    __shared__ unsigned int amLast;
    if (tid == 0) {
        __threadfence();
        amLast = (atomicAdd(&g_done, 1u) == (unsigned)(nb - 1)) ? 1u : 0u;
    }
    __syncthreads();
    if (amLast) {
        __threadfence();
        double s = 0.0;
        for (int r = tid; r < NROW; r += 256) {
            float denom = g_denom[r] - ex2f(g_self[r] * C2);  // remove diag
            int pk = (r < NHALF) ? r : (r - NHALF);
            s += (double)(__logf(denom) - 2.0f * g_pos[pk]);
        }
        #pragma unroll
        for (int o = 16; o; o >>= 1) s += __shfl_xor_sync(~0u, s, o);
        __shared__ double ws[8];
        if (lane == 0) ws[wid] = s;
        __syncthreads();
        if (tid == 0) {
            double tot = 0.0;
            #pragma unroll
            for (int i = 0; i < 8; i++) tot += ws[i];
            out[0] = (float)(tot / (double)NROW);
        }
    }
}

// ---------------------------------------------------------------------------
extern "C" void kernel_launch(void* const* d_in, const int* in_sizes, int n_in,
                              void* d_out, int out_size) {
    const float* emb_i = (const float*)d_in[0];
    const float* emb_j = (const float*)d_in[1];
    float* out = (float*)d_out;

    cudaFuncSetAttribute(sim_kernel, cudaFuncAttributeMaxDynamicSharedMemorySize,
                         SMEM_TOTAL);
    norm_pos_kernel<<<1024, 256>>>(emb_i, emb_j);
    sim_kernel<<<NB, 256, SMEM_TOTAL>>>(out);
}

// round 14
// speedup vs baseline: 1.2647x; 1.2647x over previous
#include <cuda_runtime.h>
#include <cuda_bf16.h>
#include <cstdint>
#include <math.h>

// NT-Xent loss, N=4096, D=256, T=0.5. bf16 mma.sync m16n8k16, upper-triangle,
// mbarrier-pipelined (R6 trunk sim kernel, verbatim — 72.2us config).
// Norm kernel v2: warp handles the (k, k+N) pair entirely in registers.

#define NROW 8192
#define NHALF 4096
#define DIM 256
#define NTILE 64
#define TOTAL_UT 2080               // 64*65/2
#define C2 2.885390081777927f       // 2 * log2(e)

// smem: swizzled 512B-row tiles (64KB each): A + B0 + B1 + 4 mbarriers
#define SM_A 0
#define SM_B0 65536
#define SM_B1 131072
#define SM_BAR 196608
#define SMEM_TOTAL (196608 + 64)

__device__ __nv_bfloat16 g_zh[NROW * DIM];
__device__ float g_denom[NROW];
__device__ float g_pos[NHALF];
__device__ float g_self[NROW];

// ---------------------------------------------------------------------------
__device__ __forceinline__ float ex2f(float x) {
    float y; asm("ex2.approx.ftz.f32 %0, %1;" : "=f"(y) : "f"(x)); return y;
}
__device__ __forceinline__ uint32_t smem_u32(const void* p) {
    uint32_t a;
    asm("{ .reg .u64 t; cvta.to.shared.u64 t, %1; cvt.u32.u64 %0, t; }"
        : "=r"(a) : "l"(p));
    return a;
}
__device__ __forceinline__ void cp16(uint32_t s, const void* g) {
    asm volatile("cp.async.cg.shared.global [%0], [%1], 16;" :: "r"(s), "l"(g));
}
#define CP_COMMIT() asm volatile("cp.async.commit_group;" ::: "memory")
#define CP_WAIT0()  asm volatile("cp.async.wait_group 0;" ::: "memory")

#define MBAR_INIT(a, c) \
    asm volatile("mbarrier.init.shared.b64 [%0], %1;" :: "r"(a), "r"(c) : "memory")
#define MBAR_INVAL(a) \
    asm volatile("mbarrier.inval.shared.b64 [%0];" :: "r"(a) : "memory")
#define MBAR_ARRIVE(a) \
    asm volatile("mbarrier.arrive.shared.b64 _, [%0];" :: "r"(a) : "memory")
#define CPA_NOINC(a) \
    asm volatile("cp.async.mbarrier.arrive.noinc.shared.b64 [%0];" :: "r"(a) : "memory")

#define MBAR_WAIT(mbar, ph) do {                                              \
    uint32_t _m = (mbar); uint32_t _p = (uint32_t)(ph); uint32_t _done;       \
    asm volatile("{\n\t.reg .pred p;\n\t"                                     \
        "mbarrier.try_wait.parity.shared.b64 p, [%1], %2;\n\t"                \
        "selp.b32 %0, 1, 0, p;\n\t}"                                          \
        : "=r"(_done) : "r"(_m), "r"(_p) : "memory");                         \
    if (!_done) {                                                             \
        asm volatile("{\n\t.reg .pred P1;\n\t"                                \
            "WL_%=:\n\t"                                                      \
            "mbarrier.try_wait.parity.shared.b64 P1, [%0], %1;\n\t"           \
            "@P1 bra.uni WD_%=;\n\t"                                          \
            "bra.uni WL_%=;\n\t"                                              \
            "WD_%=:\n\t}" :: "r"(_m), "r"(_p) : "memory");                    \
    }                                                                         \
} while (0)

#define LDSM4(r0, r1, r2, r3, a)                                        \
    asm volatile("ldmatrix.sync.aligned.m8n8.x4.shared.b16 "            \
                 "{%0,%1,%2,%3}, [%4];"                                 \
                 : "=r"(r0), "=r"(r1), "=r"(r2), "=r"(r3) : "r"(a))

#define MMA16816(c, a, b0, b1)                                          \
    asm volatile("mma.sync.aligned.m16n8k16.row.col.f32.bf16.bf16.f32 " \
                 "{%0,%1,%2,%3}, {%4,%5,%6,%7}, {%8,%9}, {%0,%1,%2,%3};"\
                 : "+f"((c)[0]), "+f"((c)[1]), "+f"((c)[2]), "+f"((c)[3]) \
                 : "r"((a)[0]), "r"((a)[1]), "r"((a)[2]), "r"((a)[3]),  \
                   "r"(b0), "r"(b1))

// ---------------------------------------------------------------------------
// Kernel 1 (v2): one warp per pair (k, k+N); no smem, no block barriers.
// grid = 512 x 256 (8 warps/block, 4096 warps total).
// ---------------------------------------------------------------------------
__global__ void norm_pos_kernel(const float* __restrict__ ei,
                                const float* __restrict__ ej) {
    const int tid = threadIdx.x, w = tid >> 5, lane = tid & 31;
    const int k = blockIdx.x * 8 + w;

    const float* si = ei + (size_t)k * DIM + lane * 8;
    const float* sj = ej + (size_t)k * DIM + lane * 8;
    float4 a0 = *reinterpret_cast<const float4*>(si);
    float4 a1 = *reinterpret_cast<const float4*>(si + 4);
    float4 b0 = *reinterpret_cast<const float4*>(sj);
    float4 b1 = *reinterpret_cast<const float4*>(sj + 4);
    float vi[8] = {a0.x, a0.y, a0.z, a0.w, a1.x, a1.y, a1.z, a1.w};
    float vj[8] = {b0.x, b0.y, b0.z, b0.w, b1.x, b1.y, b1.z, b1.w};

    float ni = 0.f, nj = 0.f;
    #pragma unroll
    for (int i = 0; i < 8; i++) { ni += vi[i] * vi[i]; nj += vj[i] * vj[i]; }
    #pragma unroll
    for (int o = 16; o; o >>= 1) {
        ni += __shfl_xor_sync(~0u, ni, o);
        nj += __shfl_xor_sync(~0u, nj, o);
    }
    const float invi = 1.0f / fmaxf(sqrtf(ni), 1e-8f);
    const float invj = 1.0f / fmaxf(sqrtf(nj), 1e-8f);

    float zi[8], zj[8];
    __nv_bfloat162 hbi[4], hbj[4];
    float ssi = 0.f, ssj = 0.f, pos = 0.f;
    #pragma unroll
    for (int i = 0; i < 8; i++) { zi[i] = vi[i] * invi; zj[i] = vj[i] * invj; }
    #pragma unroll
    for (int i = 0; i < 4; i++) {
        hbi[i] = __floats2bfloat162_rn(zi[2 * i], zi[2 * i + 1]);
        hbj[i] = __floats2bfloat162_rn(zj[2 * i], zj[2 * i + 1]);
        float lxi = __bfloat162float(hbi[i].x), hxi = __bfloat162float(hbi[i].y);
        float lxj = __bfloat162float(hbj[i].x), hxj = __bfloat162float(hbj[i].y);
        ssi += lxi * lxi + hxi * hxi;
        ssj += lxj * lxj + hxj * hxj;
    }
    #pragma unroll
    for (int i = 0; i < 8; i++) pos += zi[i] * zj[i];

    *reinterpret_cast<uint4*>(&g_zh[(size_t)k * DIM + lane * 8]) =
        *reinterpret_cast<uint4*>(hbi);
    *reinterpret_cast<uint4*>(&g_zh[(size_t)(k + NHALF) * DIM + lane * 8]) =
        *reinterpret_cast<uint4*>(hbj);

    #pragma unroll
    for (int o = 16; o; o >>= 1) {
        ssi += __shfl_xor_sync(~0u, ssi, o);
        ssj += __shfl_xor_sync(~0u, ssj, o);
        pos += __shfl_xor_sync(~0u, pos, o);
    }
    if (lane == 0) {
        g_self[k] = ssi;
        g_self[k + NHALF] = ssj;
        g_pos[k] = pos;
        g_denom[k] = 0.f;
        g_denom[k + NHALF] = 0.f;
    }
}

// ---------------------------------------------------------------------------
// cp.async of a 128x256 bf16 tile into 512B-row smem, 16B-chunk XOR swizzle
// (chunk c of row r stored at c ^ (r&7)). No commit here. [R6 verbatim]
// ---------------------------------------------------------------------------
__device__ __forceinline__ void fill_tile(uint32_t sdst, int zrow, int tid) {
    const __nv_bfloat16* src = g_zh + ((size_t)zrow << 8);
    #pragma unroll
    for (int i = 0; i < 16; ++i) {
        int q = tid + (i << 8);          // 16B chunk id 0..4095
        int r = q >> 5;                  // row 0..127
        int c = q & 31;                  // chunk in row
        cp16(sdst + (r << 9) + ((c ^ (r & 7)) << 4), src + ((size_t)q << 3));
    }
}

// ---------------------------------------------------------------------------
// Kernel 2: persistent upper-tri sim-GEMM + exp-sum, mbarrier-pipelined.
// [R6 verbatim — do not add code; register allocation is fragile here]
// ---------------------------------------------------------------------------
__global__ __launch_bounds__(256, 1) void sim_kernel() {
    extern __shared__ char smem[];
    const uint32_t sb = smem_u32(smem);
    const uint32_t FULL[2]  = {sb + SM_BAR,      sb + SM_BAR + 8};
    const uint32_t EMPTY[2] = {sb + SM_BAR + 16, sb + SM_BAR + 24};
    const uint32_t BUF[2]   = {sb + SM_B0, sb + SM_B1};
    const int tid = threadIdx.x, wid = tid >> 5, lane = tid & 31;
    const int wm = wid >> 2, wn = wid & 3;

    const int b = blockIdx.x, nb = gridDim.x;
    const int t0 = (b * TOTAL_UT) / nb;
    const int t1 = ((b + 1) * TOTAL_UT) / nb;
    const int nt = t1 - t0;
    if (nt <= 0) return;

    int R = 0, rem = t0;
    while (rem >= NTILE - R) { rem -= NTILE - R; R++; }
    int C = R + rem;

    if (tid == 0) {
        MBAR_INIT(FULL[0], 256); MBAR_INIT(FULL[1], 256);
        MBAR_INIT(EMPTY[0], 256); MBAR_INIT(EMPTY[1], 256);
    }
    __syncthreads();

    // per-lane ldmatrix address precompute (swizzled layout)
    const uint32_t rm  = (uint32_t)(lane & 7) << 4;        // row&7 XOR mask
    const uint32_t hiA = (uint32_t)(lane >> 4) << 4;
    const uint32_t hiB = (uint32_t)((lane >> 3) & 1) << 4;
    uint32_t aRow[4];
    #pragma unroll
    for (int mf = 0; mf < 4; ++mf)
        aRow[mf] = (uint32_t)(wm * 64 + (lane & 15) + mf * 16) << 9;
    const uint32_t rB0 = (uint32_t)(wn * 32 + (lane & 7) + ((lane >> 4) << 3));
    const uint32_t bRow0 = rB0 << 9, bRow1 = (rB0 + 16) << 9;

    float dacc[4][2];
    #pragma unroll
    for (int i = 0; i < 4; i++) { dacc[i][0] = 0.f; dacc[i][1] = 0.f; }

    int loadedR = R;
    // prologue: A + fill 0
    fill_tile(sb + SM_A, R << 7, tid);
    fill_tile(BUF[0], C << 7, tid);
    CPA_NOINC(FULL[0]);
    CP_COMMIT(); CP_WAIT0();
    __syncthreads();                     // A (and fill0) visible to all

    for (int i = 0; i < nt; ++i) {
        int Rn = R, Cn = C + 1;
        if (Cn == NTILE) { Rn = R + 1; Cn = Rn; }

        if (R != loadedR) {              // rare: flush + reload A (synced)
            #pragma unroll
            for (int mf = 0; mf < 4; ++mf)
                #pragma unroll
                for (int h = 0; h < 2; ++h) {
                    float v = dacc[mf][h];
                    v += __shfl_xor_sync(~0u, v, 1);
                    v += __shfl_xor_sync(~0u, v, 2);
                    if ((lane & 3) == 0)
                        atomicAdd(&g_denom[(loadedR << 7) + wm * 64 + mf * 16
                                           + (lane >> 2) + h * 8], v);
                    dacc[mf][h] = 0.f;
                }
            __syncthreads();
            fill_tile(sb + SM_A, R << 7, tid);
            CP_COMMIT(); CP_WAIT0();
            __syncthreads();
            loadedR = R;
        }

        // prefetch fill i+1 (buffer free after use i-1's k-loop)
        if (i + 1 < nt) {
            const int nbuf = (i + 1) & 1;
            if (i + 1 >= 2)
                MBAR_WAIT(EMPTY[nbuf], ((((i + 1) >> 1) - 1) & 1));
            fill_tile(BUF[nbuf], Cn << 7, tid);
            CPA_NOINC(FULL[nbuf]);
        }

        // consume tile i
        const int cb = i & 1;
        MBAR_WAIT(FULL[cb], (i >> 1) & 1);
        const uint32_t aBase = sb + SM_A;
        const uint32_t bBase = BUF[cb];

        float acc[4][4][4];
        #pragma unroll
        for (int x = 0; x < 4; x++)
            #pragma unroll
            for (int y = 0; y < 4; y++)
                #pragma unroll
                for (int c = 0; c < 4; c++) acc[x][y][c] = 0.f;

        #pragma unroll
        for (int s = 0; s < 16; ++s) {
            const uint32_t offA = (((uint32_t)s << 5) + hiA) ^ rm;
            const uint32_t offB = (((uint32_t)s << 5) + hiB) ^ rm;
            uint32_t a[4][4];
            #pragma unroll
            for (int mf = 0; mf < 4; ++mf)
                LDSM4(a[mf][0], a[mf][1], a[mf][2], a[mf][3],
                      aBase + aRow[mf] + offA);
            uint32_t bq[2][4];
            LDSM4(bq[0][0], bq[0][1], bq[0][2], bq[0][3], bBase + bRow0 + offB);
            LDSM4(bq[1][0], bq[1][1], bq[1][2], bq[1][3], bBase + bRow1 + offB);
            #pragma unroll
            for (int mf = 0; mf < 4; ++mf)
                #pragma unroll
                for (int nf = 0; nf < 4; ++nf)
                    MMA16816(acc[mf][nf], a[mf],
                             bq[nf >> 1][(nf & 1) * 2],
                             bq[nf >> 1][(nf & 1) * 2 + 1]);
        }
        MBAR_ARRIVE(EMPTY[cb]);          // done reading this B buffer

        // epilogue (overlaps other warps' MMA): rows -> dacc; cols -> colacc
        const bool offDiag = (C != R);
        float colacc[4][2];
        #pragma unroll
        for (int x = 0; x < 4; x++) { colacc[x][0] = 0.f; colacc[x][1] = 0.f; }

        #pragma unroll
        for (int mf = 0; mf < 4; ++mf)
            #pragma unroll
            for (int nf = 0; nf < 4; ++nf)
                #pragma unroll
                for (int c = 0; c < 4; ++c) {
                    float e = ex2f(acc[mf][nf][c] * C2);
                    dacc[mf][c >> 1] += e;
                    colacc[nf][c & 1] += e;
                }

        if (offDiag) {
            #pragma unroll
            for (int nf = 0; nf < 4; ++nf)
                #pragma unroll
                for (int p = 0; p < 2; ++p) {
                    float v = colacc[nf][p];
                    v += __shfl_xor_sync(~0u, v, 4);
                    v += __shfl_xor_sync(~0u, v, 8);
                    v += __shfl_xor_sync(~0u, v, 16);
                    if (lane < 4)
                        atomicAdd(&g_denom[(C << 7) + wn * 32 + nf * 8
                                           + (lane & 3) * 2 + p], v);
                }
        }

        R = Rn; C = Cn;
    }

    // final row flush
    #pragma unroll
    for (int mf = 0; mf < 4; ++mf)
        #pragma unroll
        for (int h = 0; h < 2; ++h) {
            float v = dacc[mf][h];
            v += __shfl_xor_sync(~0u, v, 1);
            v += __shfl_xor_sync(~0u, v, 2);
            if ((lane & 3) == 0)
                atomicAdd(&g_denom[(loadedR << 7) + wm * 64 + mf * 16
                                   + (lane >> 2) + h * 8], v);
        }

    __syncthreads();
    if (tid == 0) {
        MBAR_INVAL(FULL[0]); MBAR_INVAL(FULL[1]);
        MBAR_INVAL(EMPTY[0]); MBAR_INVAL(EMPTY[1]);
    }
}

// ---------------------------------------------------------------------------
// Kernel 3: final scalar (double accumulation), 1024 threads.
// ---------------------------------------------------------------------------
__global__ void finish_kernel(float* __restrict__ out) {
    int tid = threadIdx.x;
    double s = 0.0;
    for (int r = tid; r < NROW; r += 1024) {
        float denom = g_denom[r] - ex2f(g_self[r] * C2);
        int pk = (r < NHALF) ? r : (r - NHALF);
        s += (double)(__logf(denom) - 2.0f * g_pos[pk]);
    }
    #pragma unroll
    for (int o = 16; o; o >>= 1) s += __shfl_xor_sync(~0u, s, o);
    __shared__ double ws[32];
    int lane = tid & 31, w = tid >> 5;
    if (lane == 0) ws[w] = s;
    __syncthreads();
    if (tid == 0) {
        double tot = 0.0;
        #pragma unroll
        for (int i = 0; i < 32; i++) tot += ws[i];
        out[0] = (float)(tot / (double)NROW);
    }
}

// ---------------------------------------------------------------------------
extern "C" void kernel_launch(void* const* d_in, const int* in_sizes, int n_in,
                              void* d_out, int out_size) {
    const float* emb_i = (const float*)d_in[0];
    const float* emb_j = (const float*)d_in[1];
    float* out = (float*)d_out;

    cudaFuncSetAttribute(sim_kernel, cudaFuncAttributeMaxDynamicSharedMemorySize,
                         SMEM_TOTAL);
    norm_pos_kernel<<<512, 256>>>(emb_i, emb_j);
    sim_kernel<<<148, 256, SMEM_TOTAL>>>();
    finish_kernel<<<1, 1024>>>(out);
}

// round 15
// speedup vs baseline: 1.4167x; 1.1201x over previous
#include <cuda_runtime.h>
#include <cuda_fp16.h>
#include <cstdint>
#include <math.h>

// NT-Xent loss, N=4096, D=256, T=0.5. f16 mma.sync m16n8k16 (f16 acc),
// upper-triangle symmetric, persistent kernel at OCCUPANCY 2 (2 CTAs/SM):
// smem cut to 112KB/CTA via full A (64KB) + 3-slot ring of 16KB B k-chunks.
// 8 warps = 2(M) x 4(N), warp tile 64x32 (best L1 ratio). Packed f16x2
// epilogue. Separate finish kernel (sim kernel kept minimal).

#define NROW 8192
#define NHALF 4096
#define DIM 256
#define NTILE 64
#define TOTAL_UT 2080               // 64*65/2
#define C2 2.885390081777927f       // 2 * log2(e)
#define NB 296                      // 2 CTAs per SM

// smem: A 64KB (512B rows) + 3 x 16KB B chunks (128B rows) + mbarriers
#define SM_A 0
#define SM_BC 65536
#define CHUNK_B 16384
#define SM_BAR (65536 + 3 * 16384)  // 114688
#define SMEM_TOTAL (114688 + 64)    // 112.06 KB -> 2 CTAs/SM fits 227KB

__device__ __half g_zh[NROW * DIM];          // f16 normalized rows (4 MB)
__device__ float g_denom[NROW];
__device__ float g_pos[NHALF];
__device__ float g_self[NROW];               // sum(f16(z)^2), fp32

// ---------------------------------------------------------------------------
__device__ __forceinline__ float ex2f(float x) {
    float y; asm("ex2.approx.ftz.f32 %0, %1;" : "=f"(y) : "f"(x)); return y;
}
__device__ __forceinline__ uint32_t ex2h2(uint32_t x) {
    uint32_t y; asm("ex2.approx.f16x2 %0, %1;" : "=r"(y) : "r"(x)); return y;
}
__device__ __forceinline__ uint32_t hmul2u(uint32_t a, uint32_t b) {
    uint32_t y; asm("mul.rn.f16x2 %0, %1, %2;" : "=r"(y) : "r"(a), "r"(b));
    return y;
}
__device__ __forceinline__ uint32_t hadd2u(uint32_t a, uint32_t b) {
    uint32_t y; asm("add.rn.f16x2 %0, %1, %2;" : "=r"(y) : "r"(a), "r"(b));
    return y;
}
__device__ __forceinline__ float2 unpackh2(uint32_t v) {
    __half2 h = *reinterpret_cast<__half2*>(&v);
    return make_float2(__half2float(h.x), __half2float(h.y));
}
__device__ __forceinline__ uint32_t smem_u32(const void* p) {
    uint32_t a;
    asm("{ .reg .u64 t; cvta.to.shared.u64 t, %1; cvt.u32.u64 %0, t; }"
        : "=r"(a) : "l"(p));
    return a;
}
__device__ __forceinline__ void cp16(uint32_t s, const void* g) {
    asm volatile("cp.async.cg.shared.global [%0], [%1], 16;" :: "r"(s), "l"(g));
}
#define CP_COMMIT() asm volatile("cp.async.commit_group;" ::: "memory")
#define CP_WAIT0()  asm volatile("cp.async.wait_group 0;" ::: "memory")

#define MBAR_INIT(a, c) \
    asm volatile("mbarrier.init.shared.b64 [%0], %1;" :: "r"(a), "r"(c) : "memory")
#define MBAR_INVAL(a) \
    asm volatile("mbarrier.inval.shared.b64 [%0];" :: "r"(a) : "memory")
#define MBAR_ARRIVE(a) \
    asm volatile("mbarrier.arrive.shared.b64 _, [%0];" :: "r"(a) : "memory")
#define CPA_NOINC(a) \
    asm volatile("cp.async.mbarrier.arrive.noinc.shared.b64 [%0];" :: "r"(a) : "memory")

#define MBAR_WAIT(mbar, ph) do {                                              \
    uint32_t _m = (mbar); uint32_t _p = (uint32_t)(ph); uint32_t _done;       \
    asm volatile("{\n\t.reg .pred p;\n\t"                                     \
        "mbarrier.try_wait.parity.shared.b64 p, [%1], %2;\n\t"                \
        "selp.b32 %0, 1, 0, p;\n\t}"                                          \
        : "=r"(_done) : "r"(_m), "r"(_p) : "memory");                         \
    if (!_done) {                                                             \
        asm volatile("{\n\t.reg .pred P1;\n\t"                                \
            "WL_%=:\n\t"                                                      \
            "mbarrier.try_wait.parity.shared.b64 P1, [%0], %1;\n\t"           \
            "@P1 bra.uni WD_%=;\n\t"                                          \
            "bra.uni WL_%=;\n\t"                                              \
            "WD_%=:\n\t}" :: "r"(_m), "r"(_p) : "memory");                    \
    }                                                                         \
} while (0)

#define LDSM4(r0, r1, r2, r3, a)                                        \
    asm volatile("ldmatrix.sync.aligned.m8n8.x4.shared.b16 "            \
                 "{%0,%1,%2,%3}, [%4];"                                 \
                 : "=r"(r0), "=r"(r1), "=r"(r2), "=r"(r3) : "r"(a))

// f16 x f16 -> f16 accumulate; D/C are 2 packed f16x2 regs
#define MMAF16(c, a, b0, b1)                                            \
    asm volatile("mma.sync.aligned.m16n8k16.row.col.f16.f16.f16.f16 "   \
                 "{%0,%1}, {%2,%3,%4,%5}, {%6,%7}, {%0,%1};"            \
                 : "+r"((c)[0]), "+r"((c)[1])                           \
                 : "r"((a)[0]), "r"((a)[1]), "r"((a)[2]), "r"((a)[3]),  \
                   "r"(b0), "r"(b1))

// ---------------------------------------------------------------------------
// Kernel 1 (pair-warp): one warp per pair (k, k+N); no smem, no barriers.
// grid = 512 x 256.
// ---------------------------------------------------------------------------
__global__ void norm_pos_kernel(const float* __restrict__ ei,
                                const float* __restrict__ ej) {
    const int tid = threadIdx.x, w = tid >> 5, lane = tid & 31;
    const int k = blockIdx.x * 8 + w;

    const float* si = ei + (size_t)k * DIM + lane * 8;
    const float* sj = ej + (size_t)k * DIM + lane * 8;
    float4 a0 = *reinterpret_cast<const float4*>(si);
    float4 a1 = *reinterpret_cast<const float4*>(si + 4);
    float4 b0 = *reinterpret_cast<const float4*>(sj);
    float4 b1 = *reinterpret_cast<const float4*>(sj + 4);
    float vi[8] = {a0.x, a0.y, a0.z, a0.w, a1.x, a1.y, a1.z, a1.w};
    float vj[8] = {b0.x, b0.y, b0.z, b0.w, b1.x, b1.y, b1.z, b1.w};

    float ni = 0.f, nj = 0.f;
    #pragma unroll
    for (int i = 0; i < 8; i++) { ni += vi[i] * vi[i]; nj += vj[i] * vj[i]; }
    #pragma unroll
    for (int o = 16; o; o >>= 1) {
        ni += __shfl_xor_sync(~0u, ni, o);
        nj += __shfl_xor_sync(~0u, nj, o);
    }
    const float invi = 1.0f / fmaxf(sqrtf(ni), 1e-8f);
    const float invj = 1.0f / fmaxf(sqrtf(nj), 1e-8f);

    float zi[8], zj[8];
    __half2 hbi[4], hbj[4];
    float ssi = 0.f, ssj = 0.f, pos = 0.f;
    #pragma unroll
    for (int i = 0; i < 8; i++) { zi[i] = vi[i] * invi; zj[i] = vj[i] * invj; }
    #pragma unroll
    for (int i = 0; i < 4; i++) {
        hbi[i] = __floats2half2_rn(zi[2 * i], zi[2 * i + 1]);
        hbj[i] = __floats2half2_rn(zj[2 * i], zj[2 * i + 1]);
        float lxi = __half2float(hbi[i].x), hxi = __half2float(hbi[i].y);
        float lxj = __half2float(hbj[i].x), hxj = __half2float(hbj[i].y);
        ssi += lxi * lxi + hxi * hxi;
        ssj += lxj * lxj + hxj * hxj;
    }
    #pragma unroll
    for (int i = 0; i < 8; i++) pos += zi[i] * zj[i];

    *reinterpret_cast<uint4*>(&g_zh[(size_t)k * DIM + lane * 8]) =
        *reinterpret_cast<uint4*>(hbi);
    *reinterpret_cast<uint4*>(&g_zh[(size_t)(k + NHALF) * DIM + lane * 8]) =
        *reinterpret_cast<uint4*>(hbj);

    #pragma unroll
    for (int o = 16; o; o >>= 1) {
        ssi += __shfl_xor_sync(~0u, ssi, o);
        ssj += __shfl_xor_sync(~0u, ssj, o);
        pos += __shfl_xor_sync(~0u, pos, o);
    }
    if (lane == 0) {
        g_self[k] = ssi;
        g_self[k + NHALF] = ssj;
        g_pos[k] = pos;
        g_denom[k] = 0.f;
        g_denom[k + NHALF] = 0.f;
    }
}

// ---------------------------------------------------------------------------
// A tile fill: 128x256 f16 into 512B-row smem, 16B-chunk XOR swizzle.
// ---------------------------------------------------------------------------
__device__ __forceinline__ void fill_tile(uint32_t sdst, int zrow, int tid) {
    const __half* src = g_zh + ((size_t)zrow << 8);
    #pragma unroll
    for (int i = 0; i < 16; ++i) {
        int q = tid + (i << 8);          // 16B chunk id 0..4095
        int r = q >> 5;                  // row 0..127
        int c = q & 31;
        cp16(sdst + (r << 9) + ((c ^ (r & 7)) << 4), src + ((size_t)q << 3));
    }
}

// ---------------------------------------------------------------------------
// B k-chunk fill: 128 rows x 64 f16 (k-quarter kc) into 128B-row smem,
// 16B-chunk XOR swizzle (8 chunks/row). 256 threads x 4 cp.async.
// ---------------------------------------------------------------------------
__device__ __forceinline__ void fill_chunk(uint32_t sdst, int zrow, int kc,
                                           int tid) {
    const __half* src = g_zh + ((size_t)zrow << 8) + (kc << 6);
    #pragma unroll
    for (int i = 0; i < 4; ++i) {
        int q = tid + (i << 8);          // 0..1023
        int r = q >> 3;                  // row 0..127
        int cc = q & 7;                  // 16B chunk in row
        cp16(sdst + (r << 7) + ((cc ^ (r & 7)) << 4),
             src + ((size_t)r << 8) + (cc << 3));
    }
}

// ---------------------------------------------------------------------------
// Kernel 2: persistent upper-tri sim-GEMM + exp-sum. 296 CTAs x 256 threads,
// occupancy 2. 8 warps = 2(M) x 4(N), warp tile 64x32, f16 acc.
// B streamed as 16KB k-chunks through a 3-slot mbarrier ring (depth-2).
// ---------------------------------------------------------------------------
__global__ __launch_bounds__(256, 2) void sim_kernel() {
    extern __shared__ char smem[];
    const uint32_t sb = smem_u32(smem);
    const int tid = threadIdx.x, wid = tid >> 5, lane = tid & 31;
    const int wm = wid >> 2, wn = wid & 3;

    const int b = blockIdx.x, nb = gridDim.x;
    const int t0 = (b * TOTAL_UT) / nb;
    const int t1 = ((b + 1) * TOTAL_UT) / nb;
    const int nt = t1 - t0;
    if (nt <= 0) return;

    int R = 0, rem = t0;
    while (rem >= NTILE - R) { rem -= NTILE - R; R++; }
    int C = R + rem;

    if (tid == 0) {
        #pragma unroll
        for (int s = 0; s < 3; ++s) {
            MBAR_INIT(sb + SM_BAR + s * 8, 256);       // FULL[s]
            MBAR_INIT(sb + SM_BAR + 24 + s * 8, 256);  // EMPTY[s]
        }
    }
    __syncthreads();

    // ldmatrix addressing
    const uint32_t rm  = (uint32_t)(lane & 7) << 4;        // XOR mask (bytes)
    const uint32_t hiA = (uint32_t)(lane >> 4) << 4;
    const uint32_t hib = (uint32_t)((lane >> 3) & 1) << 4;
    uint32_t aRow[4];
    #pragma unroll
    for (int mf = 0; mf < 4; ++mf)
        aRow[mf] = (uint32_t)(wm * 64 + (lane & 15) + mf * 16) << 9;
    const uint32_t rB0 = (uint32_t)(wn * 32 + (lane & 7) + ((lane >> 4) << 3));
    const uint32_t bRow0 = rB0 << 7, bRow1 = (rB0 + 16) << 7;  // 128B rows

    __half2 c2h2v = __floats2half2_rn(C2, C2);
    const uint32_t C2H2 = *reinterpret_cast<uint32_t*>(&c2h2v);

    float dacc[4][2];
    #pragma unroll
    for (int x = 0; x < 4; x++) { dacc[x][0] = 0.f; dacc[x][1] = 0.f; }

    int loadedR = R;
    fill_tile(sb + SM_A, R << 7, tid);
    CP_COMMIT(); CP_WAIT0();
    __syncthreads();                               // A visible
    // prologue: chunks g=0 (slot 0) and g=1 (slot 1) of tile 0
    fill_chunk(sb + SM_BC, C << 7, 0, tid);
    CPA_NOINC(sb + SM_BAR);
    fill_chunk(sb + SM_BC + CHUNK_B, C << 7, 1, tid);
    CPA_NOINC(sb + SM_BAR + 8);

    const int totalChunks = nt << 2;

    for (int i = 0; i < nt; ++i) {
        int Rn = R, Cn = C + 1;
        if (Cn == NTILE) { Rn = R + 1; Cn = Rn; }

        if (R != loadedR) {              // rare: flush rows + reload A
            #pragma unroll
            for (int mf = 0; mf < 4; ++mf)
                #pragma unroll
                for (int h = 0; h < 2; ++h) {
                    float v = dacc[mf][h];
                    v += __shfl_xor_sync(~0u, v, 1);
                    v += __shfl_xor_sync(~0u, v, 2);
                    if ((lane & 3) == 0)
                        atomicAdd(&g_denom[(loadedR << 7) + wm * 64 + mf * 16
                                           + (lane >> 2) + h * 8], v);
                    dacc[mf][h] = 0.f;
                }
            __syncthreads();
            fill_tile(sb + SM_A, R << 7, tid);
            CP_COMMIT(); CP_WAIT0();
            __syncthreads();
            loadedR = R;
        }

        uint32_t acc[4][4][2];           // f16x2 packed accumulators
        #pragma unroll
        for (int x = 0; x < 4; x++)
            #pragma unroll
            for (int y = 0; y < 4; y++) { acc[x][y][0] = 0u; acc[x][y][1] = 0u; }

        #pragma unroll
        for (int c = 0; c < 4; ++c) {    // 4 k-chunks per tile
            const int g = (i << 2) + c;
            const int gp = g + 2;        // prefetch 2 ahead
            if (gp < totalChunks) {
                const int ps = gp % 3;
                if (gp >= 3)
                    MBAR_WAIT(sb + SM_BAR + 24 + ps * 8, ((gp / 3) - 1) & 1);
                const int pC = ((gp >> 2) == i) ? C : Cn;
                fill_chunk(sb + SM_BC + ps * CHUNK_B, pC << 7, gp & 3, tid);
                CPA_NOINC(sb + SM_BAR + ps * 8);
            }
            const int cs = g % 3;
            MBAR_WAIT(sb + SM_BAR + cs * 8, (g / 3) & 1);
            const uint32_t bBase = sb + SM_BC + cs * CHUNK_B;

            #pragma unroll
            for (int sl = 0; sl < 4; ++sl) {
                const int s = (c << 2) + sl;
                const uint32_t offA = (((uint32_t)s << 5) + hiA) ^ rm;
                const uint32_t offB = (((uint32_t)sl << 5) + hib) ^ rm;
                uint32_t a[4][4];
                #pragma unroll
                for (int mf = 0; mf < 4; ++mf)
                    LDSM4(a[mf][0], a[mf][1], a[mf][2], a[mf][3],
                          sb + SM_A + aRow[mf] + offA);
                uint32_t bq[2][4];
                LDSM4(bq[0][0], bq[0][1], bq[0][2], bq[0][3],
                      bBase + bRow0 + offB);
                LDSM4(bq[1][0], bq[1][1], bq[1][2], bq[1][3],
                      bBase + bRow1 + offB);
                #pragma unroll
                for (int mf = 0; mf < 4; ++mf)
                    #pragma unroll
                    for (int nf = 0; nf < 4; ++nf)
                        MMAF16(acc[mf][nf], a[mf],
                               bq[nf >> 1][(nf & 1) * 2],
                               bq[nf >> 1][(nf & 1) * 2 + 1]);
            }
            MBAR_ARRIVE(sb + SM_BAR + 24 + cs * 8);   // release chunk slot
        }

        // packed epilogue: exp2(C2*sim) via f16x2; rows->dacc, cols->colpk
        const bool offDiag = (C != R);
        uint32_t colpk[4] = {0u, 0u, 0u, 0u};

        #pragma unroll
        for (int mf = 0; mf < 4; ++mf)
            #pragma unroll
            for (int nf = 0; nf < 4; ++nf)
                #pragma unroll
                for (int h = 0; h < 2; ++h) {
                    uint32_t e2 = ex2h2(hmul2u(acc[mf][nf][h], C2H2));
                    colpk[nf] = hadd2u(colpk[nf], e2);
                    float2 ef = unpackh2(e2);
                    dacc[mf][h] += ef.x + ef.y;
                }

        if (offDiag) {
            #pragma unroll
            for (int nf = 0; nf < 4; ++nf) {
                uint32_t v = colpk[nf];
                v = hadd2u(v, __shfl_xor_sync(~0u, v, 4));
                v = hadd2u(v, __shfl_xor_sync(~0u, v, 8));
                v = hadd2u(v, __shfl_xor_sync(~0u, v, 16));
                if (lane < 4) {
                    float2 cf = unpackh2(v);
                    int cbase = (C << 7) + wn * 32 + nf * 8 + (lane & 3) * 2;
                    atomicAdd(&g_denom[cbase], cf.x);
                    atomicAdd(&g_denom[cbase + 1], cf.y);
                }
            }
        }

        R = Rn; C = Cn;
    }

    // final row flush
    #pragma unroll
    for (int mf = 0; mf < 4; ++mf)
        #pragma unroll
        for (int h = 0; h < 2; ++h) {
            float v = dacc[mf][h];
            v += __shfl_xor_sync(~0u, v, 1);
            v += __shfl_xor_sync(~0u, v, 2);
            if ((lane & 3) == 0)
                atomicAdd(&g_denom[(loadedR << 7) + wm * 64 + mf * 16
                                   + (lane >> 2) + h * 8], v);
        }

    __syncthreads();
    if (tid == 0) {
        #pragma unroll
        for (int s = 0; s < 3; ++s) {
            MBAR_INVAL(sb + SM_BAR + s * 8);
            MBAR_INVAL(sb + SM_BAR + 24 + s * 8);
        }
    }
}

// ---------------------------------------------------------------------------
// Kernel 3: final scalar (double accumulation), 1024 threads.
// ---------------------------------------------------------------------------
__global__ void finish_kernel(float* __restrict__ out) {
    int tid = threadIdx.x;
    double s = 0.0;
    for (int r = tid; r < NROW; r += 1024) {
        float denom = g_denom[r] - ex2f(g_self[r] * C2);
        int pk = (r < NHALF) ? r : (r - NHALF);
        s += (double)(__logf(denom) - 2.0f * g_pos[pk]);
    }
    #pragma unroll
    for (int o = 16; o; o >>= 1) s += __shfl_xor_sync(~0u, s, o);
    __shared__ double ws[32];
    int lane = tid & 31, w = tid >> 5;
    if (lane == 0) ws[w] = s;
    __syncthreads();
    if (tid == 0) {
        double tot = 0.0;
        #pragma unroll
        for (int i = 0; i < 32; i++) tot += ws[i];
        out[0] = (float)(tot / (double)NROW);
    }
}

// ---------------------------------------------------------------------------
extern "C" void kernel_launch(void* const* d_in, const int* in_sizes, int n_in,
                              void* d_out, int out_size) {
    const float* emb_i = (const float*)d_in[0];
    const float* emb_j = (const float*)d_in[1];
    float* out = (float*)d_out;

    cudaFuncSetAttribute(sim_kernel, cudaFuncAttributeMaxDynamicSharedMemorySize,
                         SMEM_TOTAL);
    norm_pos_kernel<<<512, 256>>>(emb_i, emb_j);
    sim_kernel<<<NB, 256, SMEM_TOTAL>>>();
    finish_kernel<<<1, 1024>>>(out);
}